// round 6
// baseline (speedup 1.0000x reference)
#include <cuda_runtime.h>
#include <cuda_bf16.h>
#include <cstdint>

// Problem constants (fixed shapes)
#define BQ  16
#define CC  256
#define HH  48
#define WW  48
#define NN  (HH*WW)      // 2304
#define KNN 8
#define KB  16           // per-thread candidate buffer (2 threads/row -> 32)
#define NCAND (2*KB)     // 32 candidates per row == warp size
#define TILE 128
#define NTILES (NN/TILE) // 18
#define RW  132          // row stride in 32-bit words for A/B/Sc (528 B)
#define RWB 528          // row stride bytes

// smem layout (bytes)
#define SMB_A  0
#define SMB_B  67584
#define SMB_SC 135168
#define SMB_SQ 202752
#define SMB_TOT (202752 + 512)

// Scratch (device globals; no allocation allowed)
__device__ float          g_nodesT[BQ * NN * CC];   // [B][N][C] fp32 features
__device__ __nv_bfloat16  g_bf16[BQ * NN * CC];     // bf16 copy for filter GEMM
__device__ float          g_sq[BQ * NN];            // squared norms (fp32)
__device__ int            g_cand[BQ * NN * NCAND];  // bf16-filtered candidates

__device__ __forceinline__ uint32_t smem_u32(const void* p) {
    uint32_t a;
    asm("{ .reg .u64 t; cvta.to.shared.u64 t, %1; cvt.u32.u64 %0, t; }"
        : "=r"(a) : "l"(p));
    return a;
}
#define CP_ASYNC16(dst, src) \
    asm volatile("cp.async.cg.shared.global [%0], [%1], 16;" :: "r"(dst), "l"(src))
#define CP_COMMIT() asm volatile("cp.async.commit_group;" ::: "memory")
#define CP_WAIT0()  asm volatile("cp.async.wait_group 0;" ::: "memory")

#define LDSM_X4(r0, r1, r2, r3, addr) \
    asm volatile("ldmatrix.sync.aligned.m8n8.x4.shared.b16 {%0,%1,%2,%3}, [%4];" \
        : "=r"(r0), "=r"(r1), "=r"(r2), "=r"(r3) : "r"(addr))

// ---------------------------------------------------------------------------
// Kernel 1: transpose F[b][c][n] -> nodesT[b][n][c] (fp32 + bf16 copies)
// ---------------------------------------------------------------------------
__global__ void k_transpose(const float* __restrict__ F) {
    __shared__ float t[32][33];
    int b  = blockIdx.z;
    int n0 = blockIdx.x * 32;
    int c0 = blockIdx.y * 32;
    const float* Fb = F + (size_t)b * CC * NN;
    int tx = threadIdx.x, ty = threadIdx.y;  // 32 x 8
#pragma unroll
    for (int i = 0; i < 32; i += 8)
        t[ty + i][tx] = Fb[(size_t)(c0 + ty + i) * NN + n0 + tx];
    __syncthreads();
    float* out = g_nodesT + (size_t)b * NN * CC;
    __nv_bfloat16* outb = g_bf16 + (size_t)b * NN * CC;
#pragma unroll
    for (int i = 0; i < 32; i += 8) {
        float v = t[tx][ty + i];
        size_t o = (size_t)(n0 + ty + i) * CC + c0 + tx;
        out[o]  = v;
        outb[o] = __float2bfloat16(v);
    }
}

// ---------------------------------------------------------------------------
// Kernel 2: squared norms sq[b][n]
// ---------------------------------------------------------------------------
__global__ void k_sq(const float* __restrict__ F) {
    int gid = blockIdx.x * blockDim.x + threadIdx.x;
    if (gid >= BQ * NN) return;
    int b = gid / NN, n = gid % NN;
    const float* Fb = F + (size_t)b * CC * NN + n;
    float s = 0.f;
#pragma unroll 8
    for (int c = 0; c < CC; ++c) {
        float v = Fb[(size_t)c * NN];
        s += v * v;
    }
    g_sq[gid] = s;
}

// ---------------------------------------------------------------------------
// Kernel 3: bf16 mma.m16n8k16 Gram + per-half top-16 candidate filter.
// CTA = (b, 128-row stripe); 256 thr = 8 warps (4 wm x 2 wn); warp tile 32x64.
// A[128x256] resident in smem (loaded once); B[128x256] per j-tile (cp.async,
// prefetched during previous tile's scan). ldmatrix fragments, no syncs
// inside the 16-step K loop.
// ---------------------------------------------------------------------------
__global__ __launch_bounds__(256, 1) void k_gram_topk_mma() {
    extern __shared__ unsigned char smraw[];
    const uint32_t smb = smem_u32(smraw);
    float* Sc  = (float*)(smraw + SMB_SC);   // [128][132] fp32 scores
    float* sqs = (float*)(smraw + SMB_SQ);   // [128]

    const int b   = blockIdx.y;
    const int i0  = blockIdx.x * TILE;
    const int tid = threadIdx.x;
    const int wid  = tid >> 5;
    const int lane = tid & 31;
    const int wm = wid >> 1;       // 0..3
    const int wn = wid & 1;        // 0..1
    const int grp = lane >> 2;     // 0..7
    const int tig = lane & 3;      // 0..3
    const __nv_bfloat16* Hb = g_bf16 + (size_t)b * NN * CC;

    // copy geometry: 2 threads per row, 256B halves
    const int crow = tid >> 1;
    const int chalf = tid & 1;

    // issue A stripe copy (once) + B tile 0 copy, one group
    {
        const char* asrc = (const char*)(Hb + (size_t)(i0 + crow) * CC) + chalf * 256;
        uint32_t adst = smb + SMB_A + crow * RWB + chalf * 256;
        const char* bsrc = (const char*)(Hb + (size_t)crow * CC) + chalf * 256;
        uint32_t bdst = smb + SMB_B + crow * RWB + chalf * 256;
#pragma unroll
        for (int i = 0; i < 16; ++i) {
            CP_ASYNC16(adst + i * 16, asrc + i * 16);
            CP_ASYNC16(bdst + i * 16, bsrc + i * 16);
        }
        CP_COMMIT();
    }

    // ldmatrix per-lane base addresses
    const int quad = lane >> 3;    // 0..3
    const int wi   = lane & 7;
    uint32_t aaddr[2], baddr[4];
#pragma unroll
    for (int mt = 0; mt < 2; ++mt) {
        int row = wm * 32 + mt * 16 + wi + 8 * (quad & 1);
        aaddr[mt] = smb + SMB_A + row * RWB + (quad >> 1) * 16;
    }
#pragma unroll
    for (int p = 0; p < 4; ++p) {
        int row = wn * 64 + p * 16 + wi + 8 * (quad >> 1);
        baddr[p] = smb + SMB_B + row * RWB + (quad & 1) * 16;
    }

    // per-thread top-16 ([0]=worst)
    float ts[KB];
    int   ti[KB];
#pragma unroll
    for (int k = 0; k < KB; ++k) { ts[k] = 3.0e38f; ti[k] = 0; }
    const int srow  = tid >> 1;
    const int shalf = tid & 1;
    const int ig    = i0 + srow;

    for (int jt = 0; jt < NTILES; ++jt) {
        const int j0 = jt * TILE;

        CP_WAIT0();
        __syncthreads();   // B(jt) (and A on jt=0) visible to all

        float acc[2][8][4];
#pragma unroll
        for (int mt = 0; mt < 2; ++mt)
#pragma unroll
            for (int nt = 0; nt < 8; ++nt)
#pragma unroll
                for (int q = 0; q < 4; ++q) acc[mt][nt][q] = 0.f;

        // ---- 16 k-steps, no internal syncs ----
#pragma unroll 4
        for (int ks = 0; ks < 16; ++ks) {
            const int ko = ks * 32;  // bytes per k16 step (16 bf16)
            uint32_t a[2][4];
#pragma unroll
            for (int mt = 0; mt < 2; ++mt)
                LDSM_X4(a[mt][0], a[mt][1], a[mt][2], a[mt][3], aaddr[mt] + ko);
            uint32_t bb[4][4];
#pragma unroll
            for (int p = 0; p < 4; ++p)
                LDSM_X4(bb[p][0], bb[p][1], bb[p][2], bb[p][3], baddr[p] + ko);
#pragma unroll
            for (int mt = 0; mt < 2; ++mt)
#pragma unroll
                for (int p = 0; p < 4; ++p) {
                    asm volatile(
                        "mma.sync.aligned.m16n8k16.row.col.f32.bf16.bf16.f32 "
                        "{%0,%1,%2,%3}, {%4,%5,%6,%7}, {%8,%9}, {%0,%1,%2,%3};"
                        : "+f"(acc[mt][2*p][0]), "+f"(acc[mt][2*p][1]),
                          "+f"(acc[mt][2*p][2]), "+f"(acc[mt][2*p][3])
                        : "r"(a[mt][0]), "r"(a[mt][1]), "r"(a[mt][2]), "r"(a[mt][3]),
                          "r"(bb[p][0]), "r"(bb[p][1]));
                    asm volatile(
                        "mma.sync.aligned.m16n8k16.row.col.f32.bf16.bf16.f32 "
                        "{%0,%1,%2,%3}, {%4,%5,%6,%7}, {%8,%9}, {%0,%1,%2,%3};"
                        : "+f"(acc[mt][2*p+1][0]), "+f"(acc[mt][2*p+1][1]),
                          "+f"(acc[mt][2*p+1][2]), "+f"(acc[mt][2*p+1][3])
                        : "r"(a[mt][0]), "r"(a[mt][1]), "r"(a[mt][2]), "r"(a[mt][3]),
                          "r"(bb[p][2]), "r"(bb[p][3]));
                }
        }

        __syncthreads();   // all warps done reading B(jt)

        // stage scores; load sqs; prefetch B(jt+1)
#pragma unroll
        for (int mt = 0; mt < 2; ++mt) {
            const int r0 = wm * 32 + mt * 16 + grp;
#pragma unroll
            for (int nt = 0; nt < 8; ++nt) {
                const int c0 = wn * 64 + nt * 8 + 2 * tig;
                *(float2*)&Sc[r0 * RW + c0] =
                    make_float2(acc[mt][nt][0], acc[mt][nt][1]);
                *(float2*)&Sc[(r0 + 8) * RW + c0] =
                    make_float2(acc[mt][nt][2], acc[mt][nt][3]);
            }
        }
        if (tid < TILE) sqs[tid] = g_sq[b * NN + j0 + tid];

        if (jt + 1 < NTILES) {
            const char* bsrc =
                (const char*)(Hb + (size_t)((jt + 1) * TILE + crow) * CC) + chalf * 256;
            uint32_t bdst = smb + SMB_B + crow * RWB + chalf * 256;
#pragma unroll
            for (int i = 0; i < 16; ++i) CP_ASYNC16(bdst + i * 16, bsrc + i * 16);
        }
        CP_COMMIT();
        __syncthreads();   // Sc + sqs staged

        // scan: key = sq[j] - 2*dot (sq[i] constant per row)
        const float* srcrow = &Sc[srow * RW + shalf * 64];
        const float* sqrow  = &sqs[shalf * 64];
        const int jbase = j0 + shalf * 64;
        for (int s = 0; s < 64; ++s) {
            int j = jbase + s;
            float key = sqrow[s] - 2.0f * srcrow[s];
            if (j != ig && key < ts[0]) {
                ts[0] = key; ti[0] = j;
#pragma unroll
                for (int t2 = 0; t2 < KB - 1; ++t2) {
                    if (ts[t2] < ts[t2 + 1]) {
                        float tf = ts[t2]; ts[t2] = ts[t2 + 1]; ts[t2 + 1] = tf;
                        int   tn = ti[t2]; ti[t2] = ti[t2 + 1]; ti[t2 + 1] = tn;
                    }
                }
            }
        }
        // cp.async of B(jt+1) still in flight; next iteration waits for it.
    }

    // write 16 candidates per half (rescore picks exact top-8)
    {
        int base = ((b * NN + ig) * 2 + shalf) * KB;
#pragma unroll
        for (int k = 0; k < KB; ++k) g_cand[base + k] = ti[k];
    }
}

// ---------------------------------------------------------------------------
// Kernel 4: fused exact rescore (32 cand -> top-8) + aggregation + LayerNorm.
// ---------------------------------------------------------------------------
__global__ __launch_bounds__(256) void k_refine(const float* __restrict__ gamma,
                                                const float* __restrict__ beta,
                                                float* __restrict__ out) {
    const int b    = blockIdx.y;
    const int wid  = threadIdx.x >> 5;
    const int lane = threadIdx.x & 31;
    const int n0   = blockIdx.x * 8;
    const int n    = n0 + wid;
    const int h = n / WW, w = n % WW;
    const float* Nb = g_nodesT + (size_t)b * NN * CC;

    const float* xi = Nb + (size_t)n * CC + lane * 8;
    float4 x0 = *(const float4*)xi;
    float4 x1 = *(const float4*)(xi + 4);

    // ---- exact rescore of 32 candidates (one per lane) ----
    int cand = g_cand[(b * NN + n) * NCAND + lane];
    float mykey = 3.0e38f;
    int   myidx = cand;
#pragma unroll
    for (int k = 0; k < NCAND; ++k) {
        int j = __shfl_sync(0xffffffffu, cand, k);
        const float* xj = Nb + (size_t)j * CC + lane * 8;
        float4 y0 = *(const float4*)xj;
        float4 y1 = *(const float4*)(xj + 4);
        float p = x0.x * y0.x + x0.y * y0.y + x0.z * y0.z + x0.w * y0.w
                + x1.x * y1.x + x1.y * y1.y + x1.z * y1.z + x1.w * y1.w;
#pragma unroll
        for (int o = 16; o > 0; o >>= 1) p += __shfl_xor_sync(0xffffffffu, p, o);
        if (lane == k) mykey = g_sq[b * NN + j] - 2.0f * p;
    }

    // ---- select 8 smallest; indices broadcast to all lanes ----
    int knn_j[KNN];
#pragma unroll
    for (int t = 0; t < KNN; ++t) {
        float v = mykey;
#pragma unroll
        for (int o = 16; o > 0; o >>= 1) v = fminf(v, __shfl_xor_sync(0xffffffffu, v, o));
        unsigned m = __ballot_sync(0xffffffffu, mykey == v);
        int src = __ffs(m) - 1;
        knn_j[t] = __shfl_sync(0xffffffffu, myidx, src);
        if (lane == src) mykey = 3.0e38f;
    }

    // ---- aggregate: 4-neighborhood grid + 8 knn, mean; residual ----
    float acc[8];
#pragma unroll
    for (int r = 0; r < 8; ++r) acc[r] = 0.f;
    int cnt = KNN;
#pragma unroll
    for (int t = 0; t < KNN; ++t) {
        const float* p = Nb + (size_t)knn_j[t] * CC + lane * 8;
        float4 y0 = *(const float4*)p;
        float4 y1 = *(const float4*)(p + 4);
        acc[0] += y0.x; acc[1] += y0.y; acc[2] += y0.z; acc[3] += y0.w;
        acc[4] += y1.x; acc[5] += y1.y; acc[6] += y1.z; acc[7] += y1.w;
    }
    if (w > 0)      { const float* p = Nb + (size_t)(n - 1)  * CC + lane * 8;
        float4 y0 = *(const float4*)p; float4 y1 = *(const float4*)(p + 4);
        acc[0]+=y0.x; acc[1]+=y0.y; acc[2]+=y0.z; acc[3]+=y0.w;
        acc[4]+=y1.x; acc[5]+=y1.y; acc[6]+=y1.z; acc[7]+=y1.w; cnt++; }
    if (w < WW - 1) { const float* p = Nb + (size_t)(n + 1)  * CC + lane * 8;
        float4 y0 = *(const float4*)p; float4 y1 = *(const float4*)(p + 4);
        acc[0]+=y0.x; acc[1]+=y0.y; acc[2]+=y0.z; acc[3]+=y0.w;
        acc[4]+=y1.x; acc[5]+=y1.y; acc[6]+=y1.z; acc[7]+=y1.w; cnt++; }
    if (h > 0)      { const float* p = Nb + (size_t)(n - WW) * CC + lane * 8;
        float4 y0 = *(const float4*)p; float4 y1 = *(const float4*)(p + 4);
        acc[0]+=y0.x; acc[1]+=y0.y; acc[2]+=y0.z; acc[3]+=y0.w;
        acc[4]+=y1.x; acc[5]+=y1.y; acc[6]+=y1.z; acc[7]+=y1.w; cnt++; }
    if (h < HH - 1) { const float* p = Nb + (size_t)(n + WW) * CC + lane * 8;
        float4 y0 = *(const float4*)p; float4 y1 = *(const float4*)(p + 4);
        acc[0]+=y0.x; acc[1]+=y0.y; acc[2]+=y0.z; acc[3]+=y0.w;
        acc[4]+=y1.x; acc[5]+=y1.y; acc[6]+=y1.z; acc[7]+=y1.w; cnt++; }

    const float inv = 1.0f / (float)cnt;
    float xv[8] = {x0.x, x0.y, x0.z, x0.w, x1.x, x1.y, x1.z, x1.w};
    float y[8];
#pragma unroll
    for (int r = 0; r < 8; ++r) y[r] = acc[r] * inv + xv[r];

    // ---- LayerNorm over channels ----
    float s = 0.f;
#pragma unroll
    for (int r = 0; r < 8; ++r) s += y[r];
#pragma unroll
    for (int o = 16; o > 0; o >>= 1) s += __shfl_xor_sync(0xffffffffu, s, o);
    const float mu = s * (1.0f / CC);
    float v = 0.f;
#pragma unroll
    for (int r = 0; r < 8; ++r) { float d = y[r] - mu; v += d * d; }
#pragma unroll
    for (int o = 16; o > 0; o >>= 1) v += __shfl_xor_sync(0xffffffffu, v, o);
    const float rs = rsqrtf(v * (1.0f / CC) + 1e-5f);

    __shared__ float st[8][CC];
#pragma unroll
    for (int r = 0; r < 8; ++r) {
        int c = lane * 8 + r;
        st[wid][c] = (y[r] - mu) * rs * gamma[c] + beta[c];
    }
    __syncthreads();

    const int c = threadIdx.x;
    float4 v0 = make_float4(st[0][c], st[1][c], st[2][c], st[3][c]);
    float4 v1 = make_float4(st[4][c], st[5][c], st[6][c], st[7][c]);
    size_t o = (size_t)b * CC * NN + (size_t)c * NN + n0;
    *(float4*)&out[o]     = v0;
    *(float4*)&out[o + 4] = v1;
}

// ---------------------------------------------------------------------------
extern "C" void kernel_launch(void* const* d_in, const int* in_sizes, int n_in,
                              void* d_out, int out_size) {
    const float* F     = (const float*)d_in[0];
    const float* gamma = (const float*)d_in[1];
    const float* beta  = (const float*)d_in[2];
    float* out = (float*)d_out;
    (void)in_sizes; (void)n_in; (void)out_size;

    k_transpose<<<dim3(NN / 32, CC / 32, BQ), dim3(32, 8)>>>(F);
    k_sq<<<(BQ * NN + 255) / 256, 256>>>(F);

    cudaFuncSetAttribute(k_gram_topk_mma,
                         cudaFuncAttributeMaxDynamicSharedMemorySize, SMB_TOT);
    k_gram_topk_mma<<<dim3(NTILES, BQ), 256, SMB_TOT>>>();

    k_refine<<<dim3(NN / 8, BQ), 256>>>(gamma, beta, out);
}

// round 7
// speedup vs baseline: 1.3524x; 1.3524x over previous
#include <cuda_runtime.h>
#include <cuda_fp16.h>
#include <cstdint>

// Problem constants (fixed shapes)
#define BQ  16
#define CC  256
#define HH  48
#define WW  48
#define NN  (HH*WW)      // 2304
#define KNN 8
#define KB  16           // per-thread candidate buffer (2 threads/row -> 32)
#define NCAND (2*KB)     // 32 candidates per row == warp size
#define TILE 128
#define NTILES (NN/TILE) // 18
#define NCHUNK (NTILES*4)

// gram smem layout (bytes)
#define CRW    144                 // chunk row bytes (64 fp16 + 8 pad)
#define CHUNK  (128*CRW)           // 18432
#define SMB_A0 0
#define SMB_A1 18432
#define SMB_B0 36864
#define SMB_B1 55296
#define SMB_SC 73728               // half[128][130] = 33280
#define SCH2   65                  // Sc row stride in half2
#define SMB_SQ 107008              // float[128]
#define SMB_TOT 107520

// Scratch (device globals; no allocation allowed)
__device__ __align__(256) float  g_nodesT[BQ * NN * CC];  // fp32 features [B][N][C]
__device__ __align__(256) __half g_half[BQ * NN * CC];    // fp16 copy for filter GEMM
__device__ __align__(256) float  g_sq[BQ * NN];           // squared norms
__device__ __align__(256) int    g_cand[BQ * NN * NCAND]; // filtered candidates

__device__ __forceinline__ uint32_t smem_u32(const void* p) {
    uint32_t a;
    asm("{ .reg .u64 t; cvta.to.shared.u64 t, %1; cvt.u32.u64 %0, t; }"
        : "=r"(a) : "l"(p));
    return a;
}
#define CP_ASYNC16(dst, src) \
    asm volatile("cp.async.cg.shared.global [%0], [%1], 16;" :: "r"(dst), "l"(src))
#define CP_COMMIT() asm volatile("cp.async.commit_group;" ::: "memory")
#define CP_WAIT(n)  asm volatile("cp.async.wait_group %0;" :: "n"(n) : "memory")

#define LDSM_X4(r0, r1, r2, r3, addr) \
    asm volatile("ldmatrix.sync.aligned.m8n8.x4.shared.b16 {%0,%1,%2,%3}, [%4];" \
        : "=r"(r0), "=r"(r1), "=r"(r2), "=r"(r3) : "r"(addr))

#define HMMA16(acc0, acc1, a0, a1, a2, a3, b0, b1) \
    asm volatile("mma.sync.aligned.m16n8k16.row.col.f16.f16.f16.f16 " \
        "{%0,%1}, {%2,%3,%4,%5}, {%6,%7}, {%0,%1};" \
        : "+r"(acc0), "+r"(acc1) \
        : "r"(a0), "r"(a1), "r"(a2), "r"(a3), "r"(b0), "r"(b1))

// ---------------------------------------------------------------------------
// Kernel 1: transpose F[b][c][n] -> nodesT[b][n][c] (fp32 + fp16 copies)
// ---------------------------------------------------------------------------
__global__ void k_transpose(const float* __restrict__ F) {
    __shared__ float t[32][33];
    int b  = blockIdx.z;
    int n0 = blockIdx.x * 32;
    int c0 = blockIdx.y * 32;
    const float* Fb = F + (size_t)b * CC * NN;
    int tx = threadIdx.x, ty = threadIdx.y;  // 32 x 8
#pragma unroll
    for (int i = 0; i < 32; i += 8)
        t[ty + i][tx] = Fb[(size_t)(c0 + ty + i) * NN + n0 + tx];
    __syncthreads();
    float* out = g_nodesT + (size_t)b * NN * CC;
    __half* outh = g_half + (size_t)b * NN * CC;
#pragma unroll
    for (int i = 0; i < 32; i += 8) {
        float v = t[tx][ty + i];
        size_t o = (size_t)(n0 + ty + i) * CC + c0 + tx;
        out[o]  = v;
        outh[o] = __float2half(v);
    }
}

// ---------------------------------------------------------------------------
// Kernel 2: squared norms sq[b][n]
// ---------------------------------------------------------------------------
__global__ void k_sq(const float* __restrict__ F) {
    int gid = blockIdx.x * blockDim.x + threadIdx.x;
    if (gid >= BQ * NN) return;
    int b = gid / NN, n = gid % NN;
    const float* Fb = F + (size_t)b * CC * NN + n;
    float s = 0.f;
#pragma unroll 8
    for (int c = 0; c < CC; ++c) {
        float v = Fb[(size_t)c * NN];
        s += v * v;
    }
    g_sq[gid] = s;
}

// ---------------------------------------------------------------------------
// Kernel 3: fp16 mma.m16n8k16 (fp16 acc) Gram + per-half top-16 filter.
// CTA = (b, 128-row stripe); 256 thr = 8 warps (4 wm x 2 wn); warp tile 32x64.
// A and B processed in 128x64 K-chunks, double-buffered via cp.async:
// chunk q+1 load issued before MMA of chunk q (loads fully hidden).
// Scores staged as half2 (the native fp16-acc fragment), scanned 2 thr/row.
// smem 107,520 B -> 2 CTAs/SM.
// ---------------------------------------------------------------------------
__global__ __launch_bounds__(256, 2) void k_gram_topk_mma() {
    extern __shared__ unsigned char smraw[];
    const uint32_t smb = smem_u32(smraw);
    uint32_t* Scw = (uint32_t*)(smraw + SMB_SC);  // half2[128][65]
    float*    sqs = (float*)(smraw + SMB_SQ);

    const int b   = blockIdx.y;
    const int i0  = blockIdx.x * TILE;
    const int tid = threadIdx.x;
    const int wid  = tid >> 5;
    const int lane = tid & 31;
    const int wm = wid >> 1;       // 0..3
    const int wn = wid & 1;        // 0..1
    const int grp = lane >> 2;     // 0..7
    const int tig = lane & 3;      // 0..3
    const int quad = lane >> 3;    // 0..3
    const int wi   = lane & 7;
    const __half* Hb = g_half + (size_t)b * NN * CC;

    // chunk copy geometry: 2 threads per row, 64B halves
    const int crow  = tid >> 1;
    const int chalf = tid & 1;

    // ldmatrix per-lane offsets (within a chunk buffer)
    uint32_t aoff[2], boff[4];
#pragma unroll
    for (int mt = 0; mt < 2; ++mt) {
        int row = wm * 32 + mt * 16 + wi + 8 * (quad & 1);
        aoff[mt] = row * CRW + (quad >> 1) * 16;
    }
#pragma unroll
    for (int p = 0; p < 4; ++p) {
        int row = wn * 64 + p * 16 + wi + 8 * (quad >> 1);
        boff[p] = row * CRW + (quad & 1) * 16;
    }

    // per-thread top-16 ([0]=worst)
    float ts[KB];
    int   ti[KB];
#pragma unroll
    for (int k = 0; k < KB; ++k) { ts[k] = 3.0e38f; ti[k] = 0; }
    const int srow  = tid >> 1;
    const int shalf = tid & 1;
    const int ig    = i0 + srow;

    // issue chunk q (A chunk + B chunk -> buffer q&1), one commit group
    auto issue = [&](int q) {
        const int jt = q >> 2, c = q & 3, buf = q & 1;
        const char* asrc =
            (const char*)(Hb + (size_t)(i0 + crow) * CC + c * 64 + chalf * 32);
        const char* bsrc =
            (const char*)(Hb + (size_t)(jt * TILE + crow) * CC + c * 64 + chalf * 32);
        uint32_t adst = smb + (buf ? SMB_A1 : SMB_A0) + crow * CRW + chalf * 64;
        uint32_t bdst = smb + (buf ? SMB_B1 : SMB_B0) + crow * CRW + chalf * 64;
#pragma unroll
        for (int i = 0; i < 4; ++i) {
            CP_ASYNC16(adst + i * 16, asrc + i * 16);
            CP_ASYNC16(bdst + i * 16, bsrc + i * 16);
        }
        CP_COMMIT();
    };

    issue(0);
    int q = 0;

    for (int jt = 0; jt < NTILES; ++jt) {
        const int j0 = jt * TILE;

        uint32_t acc[2][8][2];
#pragma unroll
        for (int mt = 0; mt < 2; ++mt)
#pragma unroll
            for (int nt = 0; nt < 8; ++nt)
                acc[mt][nt][0] = acc[mt][nt][1] = 0u;

        for (int c = 0; c < 4; ++c, ++q) {
            if (q + 1 < NCHUNK) { issue(q + 1); CP_WAIT(1); }
            else                {                CP_WAIT(0); }
            __syncthreads();   // chunk q visible; prior-tile scan finished

            if (c == 0 && tid < TILE) sqs[tid] = g_sq[b * NN + j0 + tid];

            const uint32_t abase = smb + ((q & 1) ? SMB_A1 : SMB_A0);
            const uint32_t bbase = smb + ((q & 1) ? SMB_B1 : SMB_B0);
#pragma unroll
            for (int ks = 0; ks < 4; ++ks) {
                const int ko = ks * 32;
                uint32_t a[2][4];
#pragma unroll
                for (int mt = 0; mt < 2; ++mt)
                    LDSM_X4(a[mt][0], a[mt][1], a[mt][2], a[mt][3],
                            abase + aoff[mt] + ko);
                uint32_t bb[4][4];
#pragma unroll
                for (int p = 0; p < 4; ++p)
                    LDSM_X4(bb[p][0], bb[p][1], bb[p][2], bb[p][3],
                            bbase + boff[p] + ko);
#pragma unroll
                for (int mt = 0; mt < 2; ++mt)
#pragma unroll
                    for (int p = 0; p < 4; ++p) {
                        HMMA16(acc[mt][2*p][0],   acc[mt][2*p][1],
                               a[mt][0], a[mt][1], a[mt][2], a[mt][3],
                               bb[p][0], bb[p][1]);
                        HMMA16(acc[mt][2*p+1][0], acc[mt][2*p+1][1],
                               a[mt][0], a[mt][1], a[mt][2], a[mt][3],
                               bb[p][2], bb[p][3]);
                    }
            }
            __syncthreads();   // all warps done with buffer q&1
        }

        // stage scores (fp16-acc fragments are already half2)
#pragma unroll
        for (int mt = 0; mt < 2; ++mt) {
            const int r0 = wm * 32 + mt * 16 + grp;
            const int cp = wn * 32 + tig;   // half2 column base
#pragma unroll
            for (int nt = 0; nt < 8; ++nt) {
                Scw[r0 * SCH2 + cp + nt * 4]       = acc[mt][nt][0];
                Scw[(r0 + 8) * SCH2 + cp + nt * 4] = acc[mt][nt][1];
            }
        }
        __syncthreads();

        // scan: key = sq[j] - 2*dot  (sq[i] constant per row)
        const __half2* srcrow =
            (const __half2*)Scw + srow * SCH2 + shalf * 32;
        const float* sqrow = sqs + shalf * 64;
        const int jbase = j0 + shalf * 64;
#pragma unroll 4
        for (int s = 0; s < 32; ++s) {
            float2 v = __half22float2(srcrow[s]);
            int j0e = jbase + 2 * s;
            float key0 = sqrow[2 * s]     - 2.0f * v.x;
            float key1 = sqrow[2 * s + 1] - 2.0f * v.y;
            if (j0e != ig && key0 < ts[0]) {
                ts[0] = key0; ti[0] = j0e;
#pragma unroll
                for (int t2 = 0; t2 < KB - 1; ++t2)
                    if (ts[t2] < ts[t2 + 1]) {
                        float tf = ts[t2]; ts[t2] = ts[t2 + 1]; ts[t2 + 1] = tf;
                        int tn = ti[t2]; ti[t2] = ti[t2 + 1]; ti[t2 + 1] = tn;
                    }
            }
            if (j0e + 1 != ig && key1 < ts[0]) {
                ts[0] = key1; ti[0] = j0e + 1;
#pragma unroll
                for (int t2 = 0; t2 < KB - 1; ++t2)
                    if (ts[t2] < ts[t2 + 1]) {
                        float tf = ts[t2]; ts[t2] = ts[t2 + 1]; ts[t2 + 1] = tf;
                        int tn = ti[t2]; ti[t2] = ti[t2 + 1]; ti[t2 + 1] = tn;
                    }
            }
        }
        // no trailing sync needed: next tile's first chunk sync orders
        // the scan before any Sc/sqs overwrite.
    }

    // write 16 candidates per half (rescore picks exact top-8)
    {
        int base = ((b * NN + ig) * 2 + shalf) * KB;
#pragma unroll
        for (int k = 0; k < KB; ++k) g_cand[base + k] = ti[k];
    }
}

// ---------------------------------------------------------------------------
// Kernel 4: fused exact rescore (32 cand -> top-8) + aggregation + LayerNorm.
// ---------------------------------------------------------------------------
__global__ __launch_bounds__(256) void k_refine(const float* __restrict__ gamma,
                                                const float* __restrict__ beta,
                                                float* __restrict__ out) {
    const int b    = blockIdx.y;
    const int wid  = threadIdx.x >> 5;
    const int lane = threadIdx.x & 31;
    const int n0   = blockIdx.x * 8;
    const int n    = n0 + wid;
    const int h = n / WW, w = n % WW;
    const float* Nb = g_nodesT + (size_t)b * NN * CC;

    const float* xi = Nb + (size_t)n * CC + lane * 8;
    float4 x0 = *(const float4*)xi;
    float4 x1 = *(const float4*)(xi + 4);

    // ---- exact rescore of 32 candidates (one per lane) ----
    int cand = g_cand[(b * NN + n) * NCAND + lane];
    float mykey = 3.0e38f;
    int   myidx = cand;
#pragma unroll
    for (int k = 0; k < NCAND; ++k) {
        int j = __shfl_sync(0xffffffffu, cand, k);
        const float* xj = Nb + (size_t)j * CC + lane * 8;
        float4 y0 = *(const float4*)xj;
        float4 y1 = *(const float4*)(xj + 4);
        float p = x0.x * y0.x + x0.y * y0.y + x0.z * y0.z + x0.w * y0.w
                + x1.x * y1.x + x1.y * y1.y + x1.z * y1.z + x1.w * y1.w;
#pragma unroll
        for (int o = 16; o > 0; o >>= 1) p += __shfl_xor_sync(0xffffffffu, p, o);
        if (lane == k) mykey = g_sq[b * NN + j] - 2.0f * p;
    }

    // ---- select 8 smallest; indices broadcast to all lanes ----
    int knn_j[KNN];
#pragma unroll
    for (int t = 0; t < KNN; ++t) {
        float v = mykey;
#pragma unroll
        for (int o = 16; o > 0; o >>= 1) v = fminf(v, __shfl_xor_sync(0xffffffffu, v, o));
        unsigned m = __ballot_sync(0xffffffffu, mykey == v);
        int src = __ffs(m) - 1;
        knn_j[t] = __shfl_sync(0xffffffffu, myidx, src);
        if (lane == src) mykey = 3.0e38f;
    }

    // ---- aggregate: 4-neighborhood grid + 8 knn, mean; residual ----
    float acc[8];
#pragma unroll
    for (int r = 0; r < 8; ++r) acc[r] = 0.f;
    int cnt = KNN;
#pragma unroll
    for (int t = 0; t < KNN; ++t) {
        const float* p = Nb + (size_t)knn_j[t] * CC + lane * 8;
        float4 y0 = *(const float4*)p;
        float4 y1 = *(const float4*)(p + 4);
        acc[0] += y0.x; acc[1] += y0.y; acc[2] += y0.z; acc[3] += y0.w;
        acc[4] += y1.x; acc[5] += y1.y; acc[6] += y1.z; acc[7] += y1.w;
    }
    if (w > 0)      { const float* p = Nb + (size_t)(n - 1)  * CC + lane * 8;
        float4 y0 = *(const float4*)p; float4 y1 = *(const float4*)(p + 4);
        acc[0]+=y0.x; acc[1]+=y0.y; acc[2]+=y0.z; acc[3]+=y0.w;
        acc[4]+=y1.x; acc[5]+=y1.y; acc[6]+=y1.z; acc[7]+=y1.w; cnt++; }
    if (w < WW - 1) { const float* p = Nb + (size_t)(n + 1)  * CC + lane * 8;
        float4 y0 = *(const float4*)p; float4 y1 = *(const float4*)(p + 4);
        acc[0]+=y0.x; acc[1]+=y0.y; acc[2]+=y0.z; acc[3]+=y0.w;
        acc[4]+=y1.x; acc[5]+=y1.y; acc[6]+=y1.z; acc[7]+=y1.w; cnt++; }
    if (h > 0)      { const float* p = Nb + (size_t)(n - WW) * CC + lane * 8;
        float4 y0 = *(const float4*)p; float4 y1 = *(const float4*)(p + 4);
        acc[0]+=y0.x; acc[1]+=y0.y; acc[2]+=y0.z; acc[3]+=y0.w;
        acc[4]+=y1.x; acc[5]+=y1.y; acc[6]+=y1.z; acc[7]+=y1.w; cnt++; }
    if (h < HH - 1) { const float* p = Nb + (size_t)(n + WW) * CC + lane * 8;
        float4 y0 = *(const float4*)p; float4 y1 = *(const float4*)(p + 4);
        acc[0]+=y0.x; acc[1]+=y0.y; acc[2]+=y0.z; acc[3]+=y0.w;
        acc[4]+=y1.x; acc[5]+=y1.y; acc[6]+=y1.z; acc[7]+=y1.w; cnt++; }

    const float inv = 1.0f / (float)cnt;
    float xv[8] = {x0.x, x0.y, x0.z, x0.w, x1.x, x1.y, x1.z, x1.w};
    float y[8];
#pragma unroll
    for (int r = 0; r < 8; ++r) y[r] = acc[r] * inv + xv[r];

    // ---- LayerNorm over channels ----
    float s = 0.f;
#pragma unroll
    for (int r = 0; r < 8; ++r) s += y[r];
#pragma unroll
    for (int o = 16; o > 0; o >>= 1) s += __shfl_xor_sync(0xffffffffu, s, o);
    const float mu = s * (1.0f / CC);
    float v = 0.f;
#pragma unroll
    for (int r = 0; r < 8; ++r) { float d = y[r] - mu; v += d * d; }
#pragma unroll
    for (int o = 16; o > 0; o >>= 1) v += __shfl_xor_sync(0xffffffffu, v, o);
    const float rs = rsqrtf(v * (1.0f / CC) + 1e-5f);

    __shared__ float st[8][CC];
#pragma unroll
    for (int r = 0; r < 8; ++r) {
        int c = lane * 8 + r;
        st[wid][c] = (y[r] - mu) * rs * gamma[c] + beta[c];
    }
    __syncthreads();

    const int c = threadIdx.x;
    float4 v0 = make_float4(st[0][c], st[1][c], st[2][c], st[3][c]);
    float4 v1 = make_float4(st[4][c], st[5][c], st[6][c], st[7][c]);
    size_t o = (size_t)b * CC * NN + (size_t)c * NN + n0;
    *(float4*)&out[o]     = v0;
    *(float4*)&out[o + 4] = v1;
}

// ---------------------------------------------------------------------------
extern "C" void kernel_launch(void* const* d_in, const int* in_sizes, int n_in,
                              void* d_out, int out_size) {
    const float* F     = (const float*)d_in[0];
    const float* gamma = (const float*)d_in[1];
    const float* beta  = (const float*)d_in[2];
    float* out = (float*)d_out;
    (void)in_sizes; (void)n_in; (void)out_size;

    k_transpose<<<dim3(NN / 32, CC / 32, BQ), dim3(32, 8)>>>(F);
    k_sq<<<(BQ * NN + 255) / 256, 256>>>(F);

    cudaFuncSetAttribute(k_gram_topk_mma,
                         cudaFuncAttributeMaxDynamicSharedMemorySize, SMB_TOT);
    k_gram_topk_mma<<<dim3(NTILES, BQ), 256, SMB_TOT>>>();

    k_refine<<<dim3(NN / 8, BQ), 256>>>(gamma, beta, out);
}